// round 16
// baseline (speedup 1.0000x reference)
#include <cuda_runtime.h>
#include <cstdint>
#include <cstddef>

typedef unsigned long long u64;

#define HID    100
#define EMB    32
#define NOPS   14
#define NMAGS  10
#define NSTEPS 40
#define BMAX   8192
#define GSTR   (BMAX * NOPS)

// ------------- static device scratch (no allocations) -------------
__device__ float g_whhq[HID * HID * 4];                  // [j][k][gate i,f,g,o]
__device__ __align__(16) float g_gxq[25 * HID * 4];      // [a][k][gate] = x@Wih^T + bih + bhh (a=24 -> x=0)
__device__ float g_gum[(size_t)NSTEPS * GSTR];           // gumbel noise per step, flat b*K+k
__device__ float g_part[(BMAX / 64) * 32];               // per-CTA prob sums

// ------------- packed f32x2 helpers -------------
__device__ __forceinline__ u64 ffma2(u64 a, u64 b, u64 c) {
  u64 d;
  asm("fma.rn.f32x2 %0, %1, %2, %3;" : "=l"(d) : "l"(a), "l"(b), "l"(c));
  return d;
}
__device__ __forceinline__ u64 fadd2(u64 a, u64 b) {
  u64 d;
  asm("add.rn.f32x2 %0, %1, %2;" : "=l"(d) : "l"(a), "l"(b));
  return d;
}
__device__ __forceinline__ u64 pack2(float x, float y) {
  u64 d;
  asm("mov.b64 %0, {%1, %2};" : "=l"(d) : "f"(x), "f"(y));
  return d;
}
__device__ __forceinline__ void unpack2(u64 v, float& x, float& y) {
  asm("mov.b64 {%0, %1}, %2;" : "=f"(x), "=f"(y) : "l"(v));
}

// ------------- threefry2x32 (JAX-exact) -------------
__device__ __forceinline__ void tf2x32(unsigned k0, unsigned k1,
                                       unsigned x0, unsigned x1,
                                       unsigned &o0, unsigned &o1) {
  unsigned ks0 = k0, ks1 = k1, ks2 = k0 ^ k1 ^ 0x1BD11BDAu;
  x0 += ks0; x1 += ks1;
#define TFR4(a,b,c,d) \
  x0 += x1; x1 = __funnelshift_l(x1, x1, a); x1 ^= x0; \
  x0 += x1; x1 = __funnelshift_l(x1, x1, b); x1 ^= x0; \
  x0 += x1; x1 = __funnelshift_l(x1, x1, c); x1 ^= x0; \
  x0 += x1; x1 = __funnelshift_l(x1, x1, d); x1 ^= x0;
  TFR4(13,15,26,6)  x0 += ks1; x1 += ks2 + 1u;
  TFR4(17,29,16,24) x0 += ks2; x1 += ks0 + 2u;
  TFR4(13,15,26,6)  x0 += ks0; x1 += ks1 + 3u;
  TFR4(17,29,16,24) x0 += ks1; x1 += ks2 + 4u;
  TFR4(13,15,26,6)  x0 += ks2; x1 += ks0 + 5u;
#undef TFR4
  o0 = x0; o1 = x1;
}

__device__ __forceinline__ float sigf(float x) {
  // XLA LogisticExpander: 0.5 + 0.5*tanh(0.5*x)
  return fmaf(0.5f, tanhf(0.5f * x), 0.5f);
}

// ------------- prep: W_hh quad layout + (x@Wih^T + b) table -------------
__global__ void prep_kernel(const float* __restrict__ Wih, const float* __restrict__ Whh,
                            const float* __restrict__ bih, const float* __restrict__ bhh,
                            const float* __restrict__ emb) {
  int idx = blockIdx.x * 256 + threadIdx.x;
  if (idx < HID * HID) {
    int j = idx / HID, k = idx % HID;
#pragma unroll
    for (int g = 0; g < 4; g++)
      g_whhq[(j * HID + k) * 4 + g] = Whh[((size_t)(g * HID + k)) * HID + j];
  } else if (idx < HID * HID + 25 * HID) {
    int q = idx - HID * HID;
    int a = q / HID, k = q % HID;
#pragma unroll
    for (int g = 0; g < 4; g++) {
      int row = g * HID + k;
      float v = bih[row] + bhh[row];
      if (a < 24) {
        for (int e = 0; e < EMB; e++)
          v = fmaf(Wih[(size_t)row * EMB + e], emb[a * EMB + e], v);
      }
      g_gxq[(a * HID + k) * 4 + g] = v;
    }
  }
}

// ------------- gumbel precompute (partitionable threefry) -------------
__global__ void gumbel_kernel(int B) {
  int s = blockIdx.y;
  int K = (s & 1) ? NMAGS : NOPS;
  int n = B * K;
  int i = blockIdx.x * 256 + threadIdx.x;
  if (i >= n) return;
  unsigned fk0, fk1;
  tf2x32(0u, 42u, 0u, (unsigned)s, fk0, fk1);         // fold_in(key(42), s)
  unsigned b0, b1;
  tf2x32(fk0, fk1, 0u, (unsigned)i, b0, b1);          // counter (hi=0, lo=i)
  unsigned bits = b0 ^ b1;                             // 32-bit partitionable path
  float f = __uint_as_float((bits >> 9) | 0x3f800000u) - 1.0f;
  float u = fmaxf(f, 1.17549435082228751e-38f);
  g_gum[(size_t)s * GSTR + i] = -logf(-logf(u));
}

// ------------- main persistent controller -------------
// smem floats: whh 40000 | hbuf 12800 | whpO 1600 | whpM 1600 | zz 1024 | act 64
#define SM_TOTAL 57088

__global__ void __launch_bounds__(256, 1) main_kernel(
    const float* __restrict__ Wop, const float* __restrict__ bop,
    const float* __restrict__ Wmag, const float* __restrict__ bmag,
    float* __restrict__ out, int B) {
  extern __shared__ float sm[];
  float*  whh  = sm;                      // 40000: [j][k][4 gates]
  float*  hbuf = sm + 40000;              // 2 x 6400: [buf][unit*32 + lane] float2 {rowL, rowL+32}
  float2* whpO = (float2*)(sm + 52800);   // [j][8]: pair g -> (Wop[2g][j], Wop[2g+1][j])
  float2* whpM = (float2*)(sm + 54400);   // [j][8] for mag
  float*  zz   = sm + 56000;              // 1024: [row][16]
  int*    act  = (int*)(sm + 57024);      // 64

  const int tid = threadIdx.x;
  const int cta = blockIdx.x;
  const int gb  = cta * 64;

  for (int i = tid; i < HID * HID * 4; i += 256) whh[i] = g_whhq[i];
  for (int i = tid; i < 800; i += 256) {
    int j = i >> 3, g = i & 7;
    int ka = 2 * g, kb_ = 2 * g + 1;
    float a = (ka  < NOPS)  ? Wop[ka  * HID + j] : 0.f;
    float b = (kb_ < NOPS)  ? Wop[kb_ * HID + j] : 0.f;
    whpO[i] = make_float2(a, b);
    float c = (ka  < NMAGS) ? Wmag[ka  * HID + j] : 0.f;
    float d = (kb_ < NMAGS) ? Wmag[kb_ * HID + j] : 0.f;
    whpM[i] = make_float2(c, d);
  }
  __syncthreads();

  // phase-A identity: 8 warps = 8 unit blocks; each thread handles rows (lane, lane+32)
  const int lane = tid & 31, kb = tid >> 5;
  const int k0 = (kb < 7) ? kb * 13 : 87;     // block 7 overlaps block 6 (benign duplicate)

  // phase-B identity
  const int rb = tid >> 2, kg = tid & 3;

  float cregA[13], cregB[13];
  float lpsum = 0.f, entsum = 0.f;            // tid<64
  float aOp = 0.f, aMag = 0.f;                // tid<16

  int cur = 0;
  for (int s = 0; s < NSTEPS; s++) {
    const bool isOp = ((s & 1) == 0);
    const int K = isOp ? NOPS : NMAGS;
    const bool reset = ((s & 7) == 0);

    // ---------- A: LSTM cell (packed f32x2, 2 rows/thread) ----------
    {
      u64 acc[52];                           // [row2][unit13][pair2]
#pragma unroll
      for (int i = 0; i < 52; i++) acc[i] = 0ull;
      if (!reset) {
        const float2* hc = (const float2*)(hbuf + cur * 6400);
        const char* wbase = (const char*)(whh + k0 * 4);
#pragma unroll 2
        for (int j = 0; j < HID; j++) {
          float2 hp = hc[j * 32 + lane];
          u64 hA = pack2(hp.x, hp.x);
          u64 hB = pack2(hp.y, hp.y);
          const ulonglong2* wr = (const ulonglong2*)(wbase + (size_t)j * 1600);
#pragma unroll
          for (int t = 0; t < 13; t++) {
            ulonglong2 w = wr[t];
            acc[t * 2]          = ffma2(w.x, hA, acc[t * 2]);
            acc[t * 2 + 1]      = ffma2(w.y, hA, acc[t * 2 + 1]);
            acc[26 + t * 2]     = ffma2(w.x, hB, acc[26 + t * 2]);
            acc[26 + t * 2 + 1] = ffma2(w.y, hB, acc[26 + t * 2 + 1]);
          }
        }
      }
      const int aA = reset ? 24 : act[lane];
      const int aB = reset ? 24 : act[lane + 32];
      const ulonglong2* gA = ((const ulonglong2*)g_gxq) + aA * HID + k0;
      const ulonglong2* gB = ((const ulonglong2*)g_gxq) + aB * HID + k0;
      float2* hn = (float2*)(hbuf + (cur ^ 1) * 6400);
#pragma unroll
      for (int t = 0; t < 13; t++) {
        ulonglong2 ga = gA[t];
        ulonglong2 gbv = gB[t];
        u64 aif = fadd2(acc[t * 2], ga.x);
        u64 ago = fadd2(acc[t * 2 + 1], ga.y);
        u64 bif = fadd2(acc[26 + t * 2], gbv.x);
        u64 bgo = fadd2(acc[26 + t * 2 + 1], gbv.y);
        float iA, fA, gAv, oA, iB, fB, gBv2, oB;
        unpack2(aif, iA, fA); unpack2(ago, gAv, oA);
        unpack2(bif, iB, fB); unpack2(bgo, gBv2, oB);
        float cpA = reset ? 0.f : cregA[t];
        float cpB = reset ? 0.f : cregB[t];
        float ivA = sigf(iA), fvA = sigf(fA), gvA = tanhf(gAv), ovA = sigf(oA);
        float ivB = sigf(iB), fvB = sigf(fB), gvB = tanhf(gBv2), ovB = sigf(oB);
        float c2A = fvA * cpA + ivA * gvA;
        float c2B = fvB * cpB + ivB * gvB;
        cregA[t] = c2A; cregB[t] = c2B;
        hn[(k0 + t) * 32 + lane] = make_float2(ovA * tanhf(c2A), ovB * tanhf(c2B));
      }
    }
    __syncthreads();

    // ---------- B: head logits -> z (packed k-pairs) ----------
    {
      const float*  hv = hbuf + (cur ^ 1) * 6400;
      const float2* W  = isOp ? whpO : whpM;
      const float*  bb = isOp ? bop : bmag;
      const int g1 = kg, g2 = kg + 4;
      const int k1a = 2 * g1, k1b = 2 * g1 + 1, k2a = 2 * g2, k2b = 2 * g2 + 1;
      const bool v1a = k1a < K, v1b = k1b < K, v2a = k2a < K, v2b = k2b < K;
      u64 acc1 = pack2(v1a ? __ldg(bb + k1a) : 0.f, v1b ? __ldg(bb + k1b) : 0.f);
      u64 acc2 = pack2(v2a ? __ldg(bb + k2a) : 0.f, v2b ? __ldg(bb + k2b) : 0.f);
      const int hoff = (rb & 31) * 2 + (rb >> 5);
#pragma unroll 4
      for (int j = 0; j < HID; j++) {
        float h = hv[j * 64 + hoff];
        u64 h2 = pack2(h, h);
        float2 w1 = W[j * 8 + g1];
        float2 w2 = W[j * 8 + g2];
        u64 w1u, w2u;
        asm("mov.b64 %0, {%1, %2};" : "=l"(w1u) : "f"(w1.x), "f"(w1.y));
        asm("mov.b64 %0, {%1, %2};" : "=l"(w2u) : "f"(w2.x), "f"(w2.y));
        acc1 = ffma2(w1u, h2, acc1);
        acc2 = ffma2(w2u, h2, acc2);
      }
      float z0, z1, z2, z3;
      unpack2(acc1, z0, z1); unpack2(acc2, z2, z3);
      float* zr = zz + rb * 16;
      if (v1a) zr[k1a] = 2.5f * tanhf(z0);
      if (v1b) zr[k1b] = 2.5f * tanhf(z1);
      if (v2a) zr[k2a] = 2.5f * tanhf(z2);
      if (v2b) zr[k2b] = 2.5f * tanhf(z3);
    }
    __syncthreads();

    // ---------- C1: softmax / sample / bookkeeping (one thread per row) ----------
    if (tid < 64) {
      float* zr = zz + tid * 16;
      float zmax = -1e30f;
      for (int k = 0; k < K; k++) zmax = fmaxf(zmax, zr[k]);
      float S = 0.f;
      for (int k = 0; k < K; k++) S += expf(zr[k] - zmax);
      float logS = logf(S);
      const float* gr = g_gum + (size_t)s * GSTR + (size_t)(gb + tid) * K;
      float best = -1e30f; int bi = 0;
#pragma unroll 4
      for (int k = 0; k < K; k++) {
        float v = zr[k] + gr[k];
        if (v > best) { best = v; bi = k; }
      }
      float ent = 0.f, sel = 0.f;
      for (int k = 0; k < K; k++) {
        float lp = zr[k] - zmax - logS;
        float p = expf(lp);
        ent -= lp * p;
        if (k == bi) sel = lp;
        zr[k] = p;                       // reuse zz as probs
      }
      lpsum += sel;
      entsum += ent;
      out[(size_t)(gb + tid) * NSTEPS + s] = (float)bi;
      act[tid] = bi + (isOp ? 0 : NOPS);
    }
    __syncthreads();

    // ---------- C2: prob accumulation (fixed order, deterministic) ----------
    if (tid < 16) {
      int valid = isOp ? (tid < NOPS) : (tid < NMAGS);
      if (valid) {
        float t = 0.f;
#pragma unroll 8
        for (int r = 0; r < 64; r++) t += zz[r * 16 + tid];
        if (isOp) aOp += t; else aMag += t;
      }
    }
    __syncthreads();
    cur ^= 1;
  }

  const size_t base = (size_t)NSTEPS * B;
  if (tid < 64) {
    out[base + 24 + (gb + tid)] = lpsum;             // log_probs.sum(-1)
    out[base + 24 + B + (gb + tid)] = entsum;        // entropies.sum(-1)
  }
  if (tid < 16) {
    g_part[cta * 32 + tid] = aOp;
    g_part[cta * 32 + 16 + tid] = aMag;
  }
}

// ------------- final reduction of prob means -------------
__global__ void reduce_kernel(float* __restrict__ out, int B, int nCTA) {
  int k = threadIdx.x;
  size_t base = (size_t)NSTEPS * B;
  float inv = 1.0f / (20.0f * (float)B);
  if (k < NOPS) {
    float s = 0.f;
    for (int c = 0; c < nCTA; c++) s += g_part[c * 32 + k];
    out[base + k] = s * inv;
  } else if (k >= 16 && k < 16 + NMAGS) {
    int m = k - 16;
    float s = 0.f;
    for (int c = 0; c < nCTA; c++) s += g_part[c * 32 + 16 + m];
    out[base + NOPS + m] = s * inv;
  }
}

extern "C" void kernel_launch(void* const* d_in, const int* in_sizes, int n_in,
                              void* d_out, int out_size) {
  const float* emb  = (const float*)d_in[0];
  const float* Wih  = (const float*)d_in[1];
  const float* Whh  = (const float*)d_in[2];
  const float* bih  = (const float*)d_in[3];
  const float* bhh  = (const float*)d_in[4];
  const float* Wop  = (const float*)d_in[5];
  const float* bop  = (const float*)d_in[6];
  const float* Wmag = (const float*)d_in[7];
  const float* bmag = (const float*)d_in[8];
  float* out = (float*)d_out;

  int B = (out_size - 24) / 42;          // out = 40B policies + 24 means + 2B sums
  if (B <= 0 || B > BMAX) B = BMAX;
  int nCTA = B / 64;

  cudaFuncSetAttribute(main_kernel, cudaFuncAttributeMaxDynamicSharedMemorySize,
                       SM_TOTAL * (int)sizeof(float));

  prep_kernel<<<(HID * HID + 25 * HID + 255) / 256, 256>>>(Wih, Whh, bih, bhh, emb);
  dim3 gg((B * NOPS + 255) / 256, NSTEPS);
  gumbel_kernel<<<gg, 256>>>(B);
  main_kernel<<<nCTA, 256, SM_TOTAL * (int)sizeof(float)>>>(Wop, bop, Wmag, bmag, out, B);
  reduce_kernel<<<1, 32>>>(out, B, nCTA);
}

// round 17
// speedup vs baseline: 1.0068x; 1.0068x over previous
#include <cuda_runtime.h>
#include <cstdint>
#include <cstddef>

typedef unsigned long long u64;

#define HID    100
#define EMB    32
#define NOPS   14
#define NMAGS  10
#define NSTEPS 40
#define BMAX   8192
#define GSTR   (BMAX * NOPS)

// ------------- static device scratch (no allocations) -------------
__device__ float g_whhq[HID * HID * 4];                  // [j][k][gate i,f,g,o]
__device__ __align__(16) float g_gxq[25 * HID * 4];      // [a][k][gate] = x@Wih^T + bih + bhh (a=24 -> x=0)
__device__ float g_gum[(size_t)NSTEPS * GSTR];           // gumbel noise per step, flat b*K+k
__device__ float g_part[(BMAX / 64) * 32];               // per-CTA prob sums

// ------------- packed f32x2 helpers -------------
__device__ __forceinline__ u64 ffma2(u64 a, u64 b, u64 c) {
  u64 d;
  asm("fma.rn.f32x2 %0, %1, %2, %3;" : "=l"(d) : "l"(a), "l"(b), "l"(c));
  return d;
}
__device__ __forceinline__ u64 fadd2(u64 a, u64 b) {
  u64 d;
  asm("add.rn.f32x2 %0, %1, %2;" : "=l"(d) : "l"(a), "l"(b));
  return d;
}
__device__ __forceinline__ u64 pack2(float x, float y) {
  u64 d;
  asm("mov.b64 %0, {%1, %2};" : "=l"(d) : "f"(x), "f"(y));
  return d;
}
__device__ __forceinline__ void unpack2(u64 v, float& x, float& y) {
  asm("mov.b64 {%0, %1}, %2;" : "=f"(x), "=f"(y) : "l"(v));
}

// ------------- threefry2x32 (JAX-exact) -------------
__device__ __forceinline__ void tf2x32(unsigned k0, unsigned k1,
                                       unsigned x0, unsigned x1,
                                       unsigned &o0, unsigned &o1) {
  unsigned ks0 = k0, ks1 = k1, ks2 = k0 ^ k1 ^ 0x1BD11BDAu;
  x0 += ks0; x1 += ks1;
#define TFR4(a,b,c,d) \
  x0 += x1; x1 = __funnelshift_l(x1, x1, a); x1 ^= x0; \
  x0 += x1; x1 = __funnelshift_l(x1, x1, b); x1 ^= x0; \
  x0 += x1; x1 = __funnelshift_l(x1, x1, c); x1 ^= x0; \
  x0 += x1; x1 = __funnelshift_l(x1, x1, d); x1 ^= x0;
  TFR4(13,15,26,6)  x0 += ks1; x1 += ks2 + 1u;
  TFR4(17,29,16,24) x0 += ks2; x1 += ks0 + 2u;
  TFR4(13,15,26,6)  x0 += ks0; x1 += ks1 + 3u;
  TFR4(17,29,16,24) x0 += ks1; x1 += ks2 + 4u;
  TFR4(13,15,26,6)  x0 += ks2; x1 += ks0 + 5u;
#undef TFR4
  o0 = x0; o1 = x1;
}

__device__ __forceinline__ float sigf(float x) {
  // XLA LogisticExpander: 0.5 + 0.5*tanh(0.5*x)
  return fmaf(0.5f, tanhf(0.5f * x), 0.5f);
}

// ------------- prep: W_hh quad layout + (x@Wih^T + b) table -------------
__global__ void prep_kernel(const float* __restrict__ Wih, const float* __restrict__ Whh,
                            const float* __restrict__ bih, const float* __restrict__ bhh,
                            const float* __restrict__ emb) {
  int idx = blockIdx.x * 256 + threadIdx.x;
  if (idx < HID * HID) {
    int j = idx / HID, k = idx % HID;
#pragma unroll
    for (int g = 0; g < 4; g++)
      g_whhq[(j * HID + k) * 4 + g] = Whh[((size_t)(g * HID + k)) * HID + j];
  } else if (idx < HID * HID + 25 * HID) {
    int q = idx - HID * HID;
    int a = q / HID, k = q % HID;
#pragma unroll
    for (int g = 0; g < 4; g++) {
      int row = g * HID + k;
      float v = bih[row] + bhh[row];
      if (a < 24) {
        for (int e = 0; e < EMB; e++)
          v = fmaf(Wih[(size_t)row * EMB + e], emb[a * EMB + e], v);
      }
      g_gxq[(a * HID + k) * 4 + g] = v;
    }
  }
}

// ------------- gumbel precompute (partitionable threefry) -------------
__global__ void gumbel_kernel(int B) {
  int s = blockIdx.y;
  int K = (s & 1) ? NMAGS : NOPS;
  int n = B * K;
  int i = blockIdx.x * 256 + threadIdx.x;
  if (i >= n) return;
  unsigned fk0, fk1;
  tf2x32(0u, 42u, 0u, (unsigned)s, fk0, fk1);         // fold_in(key(42), s)
  unsigned b0, b1;
  tf2x32(fk0, fk1, 0u, (unsigned)i, b0, b1);          // counter (hi=0, lo=i)
  unsigned bits = b0 ^ b1;                             // 32-bit partitionable path
  float f = __uint_as_float((bits >> 9) | 0x3f800000u) - 1.0f;
  float u = fmaxf(f, 1.17549435082228751e-38f);
  g_gum[(size_t)s * GSTR + i] = -logf(-logf(u));
}

// ------------- main persistent controller -------------
// smem floats: whh 40000 | hbuf 12800 | whpO 1600 | whpM 1600 | zz 1024 | act 64
#define SM_TOTAL 57088

__global__ void __launch_bounds__(256, 1) main_kernel(
    const float* __restrict__ Wop, const float* __restrict__ bop,
    const float* __restrict__ Wmag, const float* __restrict__ bmag,
    float* __restrict__ out, int B) {
  extern __shared__ float sm[];
  float*  whh  = sm;                      // 40000: [j][k][4 gates]
  float*  hbuf = sm + 40000;              // 2 x 6400: [buf][unit*32 + lane] float2 {rowL, rowL+32}
  float2* whpO = (float2*)(sm + 52800);   // [j][8]: pair g -> (Wop[2g][j], Wop[2g+1][j])
  float2* whpM = (float2*)(sm + 54400);   // [j][8] for mag
  float*  zz   = sm + 56000;              // 1024: [row][16]
  int*    act  = (int*)(sm + 57024);      // 64

  const int tid = threadIdx.x;
  const int cta = blockIdx.x;
  const int gb  = cta * 64;

  for (int i = tid; i < HID * HID * 4; i += 256) whh[i] = g_whhq[i];
  for (int i = tid; i < 800; i += 256) {
    int j = i >> 3, g = i & 7;
    int ka = 2 * g, kb_ = 2 * g + 1;
    float a = (ka  < NOPS)  ? Wop[ka  * HID + j] : 0.f;
    float b = (kb_ < NOPS)  ? Wop[kb_ * HID + j] : 0.f;
    whpO[i] = make_float2(a, b);
    float c = (ka  < NMAGS) ? Wmag[ka  * HID + j] : 0.f;
    float d = (kb_ < NMAGS) ? Wmag[kb_ * HID + j] : 0.f;
    whpM[i] = make_float2(c, d);
  }
  __syncthreads();

  // phase-A identity: 8 warps = 8 unit blocks; each thread handles rows (lane, lane+32)
  const int lane = tid & 31, kb = tid >> 5;
  const int k0 = (kb < 7) ? kb * 13 : 87;     // block 7 overlaps block 6 (benign duplicate)

  // phase-B identity
  const int rb = tid >> 2, kg = tid & 3;

  float cregA[13], cregB[13];
  float lpsum = 0.f, entsum = 0.f;            // tid<64
  float aOp = 0.f, aMag = 0.f;                // tid<16

  int cur = 0;
  for (int s = 0; s < NSTEPS; s++) {
    const bool isOp = ((s & 1) == 0);
    const int K = isOp ? NOPS : NMAGS;
    const bool reset = ((s & 7) == 0);

    // ---------- A: LSTM cell (packed f32x2, 2 rows/thread) ----------
    {
      u64 acc[52];                           // [row2][unit13][pair2]
#pragma unroll
      for (int i = 0; i < 52; i++) acc[i] = 0ull;
      if (!reset) {
        const float2* hc = (const float2*)(hbuf + cur * 6400);
        const char* wbase = (const char*)(whh + k0 * 4);
#pragma unroll 2
        for (int j = 0; j < HID; j++) {
          float2 hp = hc[j * 32 + lane];
          u64 hA = pack2(hp.x, hp.x);
          u64 hB = pack2(hp.y, hp.y);
          const ulonglong2* wr = (const ulonglong2*)(wbase + (size_t)j * 1600);
#pragma unroll
          for (int t = 0; t < 13; t++) {
            ulonglong2 w = wr[t];
            acc[t * 2]          = ffma2(w.x, hA, acc[t * 2]);
            acc[t * 2 + 1]      = ffma2(w.y, hA, acc[t * 2 + 1]);
            acc[26 + t * 2]     = ffma2(w.x, hB, acc[26 + t * 2]);
            acc[26 + t * 2 + 1] = ffma2(w.y, hB, acc[26 + t * 2 + 1]);
          }
        }
      }
      const int aA = reset ? 24 : act[lane];
      const int aB = reset ? 24 : act[lane + 32];
      const ulonglong2* gA = ((const ulonglong2*)g_gxq) + aA * HID + k0;
      const ulonglong2* gB = ((const ulonglong2*)g_gxq) + aB * HID + k0;
      float2* hn = (float2*)(hbuf + (cur ^ 1) * 6400);
#pragma unroll
      for (int t = 0; t < 13; t++) {
        ulonglong2 ga = gA[t];
        ulonglong2 gbv = gB[t];
        u64 aif = fadd2(acc[t * 2], ga.x);
        u64 ago = fadd2(acc[t * 2 + 1], ga.y);
        u64 bif = fadd2(acc[26 + t * 2], gbv.x);
        u64 bgo = fadd2(acc[26 + t * 2 + 1], gbv.y);
        float iA, fA, gAv, oA, iB, fB, gBv2, oB;
        unpack2(aif, iA, fA); unpack2(ago, gAv, oA);
        unpack2(bif, iB, fB); unpack2(bgo, gBv2, oB);
        float cpA = reset ? 0.f : cregA[t];
        float cpB = reset ? 0.f : cregB[t];
        float ivA = sigf(iA), fvA = sigf(fA), gvA = tanhf(gAv), ovA = sigf(oA);
        float ivB = sigf(iB), fvB = sigf(fB), gvB = tanhf(gBv2), ovB = sigf(oB);
        float c2A = fvA * cpA + ivA * gvA;
        float c2B = fvB * cpB + ivB * gvB;
        cregA[t] = c2A; cregB[t] = c2B;
        hn[(k0 + t) * 32 + lane] = make_float2(ovA * tanhf(c2A), ovB * tanhf(c2B));
      }
    }
    __syncthreads();

    // ---------- B: head logits -> z (packed k-pairs) ----------
    {
      const float*  hv = hbuf + (cur ^ 1) * 6400;
      const float2* W  = isOp ? whpO : whpM;
      const float*  bb = isOp ? bop : bmag;
      const int g1 = kg, g2 = kg + 4;
      const int k1a = 2 * g1, k1b = 2 * g1 + 1, k2a = 2 * g2, k2b = 2 * g2 + 1;
      const bool v1a = k1a < K, v1b = k1b < K, v2a = k2a < K, v2b = k2b < K;
      u64 acc1 = pack2(v1a ? __ldg(bb + k1a) : 0.f, v1b ? __ldg(bb + k1b) : 0.f);
      u64 acc2 = pack2(v2a ? __ldg(bb + k2a) : 0.f, v2b ? __ldg(bb + k2b) : 0.f);
      const int hoff = (rb & 31) * 2 + (rb >> 5);
#pragma unroll 4
      for (int j = 0; j < HID; j++) {
        float h = hv[j * 64 + hoff];
        u64 h2 = pack2(h, h);
        float2 w1 = W[j * 8 + g1];
        float2 w2 = W[j * 8 + g2];
        u64 w1u, w2u;
        asm("mov.b64 %0, {%1, %2};" : "=l"(w1u) : "f"(w1.x), "f"(w1.y));
        asm("mov.b64 %0, {%1, %2};" : "=l"(w2u) : "f"(w2.x), "f"(w2.y));
        acc1 = ffma2(w1u, h2, acc1);
        acc2 = ffma2(w2u, h2, acc2);
      }
      float z0, z1, z2, z3;
      unpack2(acc1, z0, z1); unpack2(acc2, z2, z3);
      float* zr = zz + rb * 16;
      if (v1a) zr[k1a] = 2.5f * tanhf(z0);
      if (v1b) zr[k1b] = 2.5f * tanhf(z1);
      if (v2a) zr[k2a] = 2.5f * tanhf(z2);
      if (v2b) zr[k2b] = 2.5f * tanhf(z3);
    }
    __syncthreads();

    // ---------- C1: softmax / sample / bookkeeping (one thread per row) ----------
    if (tid < 64) {
      float* zr = zz + tid * 16;
      float zmax = -1e30f;
      for (int k = 0; k < K; k++) zmax = fmaxf(zmax, zr[k]);
      float S = 0.f;
      for (int k = 0; k < K; k++) S += expf(zr[k] - zmax);
      float logS = logf(S);
      const float* gr = g_gum + (size_t)s * GSTR + (size_t)(gb + tid) * K;
      float best = -1e30f; int bi = 0;
#pragma unroll 4
      for (int k = 0; k < K; k++) {
        float v = zr[k] + gr[k];
        if (v > best) { best = v; bi = k; }
      }
      float ent = 0.f, sel = 0.f;
      for (int k = 0; k < K; k++) {
        float lp = zr[k] - zmax - logS;
        float p = expf(lp);
        ent -= lp * p;
        if (k == bi) sel = lp;
        zr[k] = p;                       // reuse zz as probs
      }
      lpsum += sel;
      entsum += ent;
      out[(size_t)(gb + tid) * NSTEPS + s] = (float)bi;
      act[tid] = bi + (isOp ? 0 : NOPS);
    }
    __syncthreads();

    // ---------- C2: prob accumulation (fixed order, deterministic) ----------
    if (tid < 16) {
      int valid = isOp ? (tid < NOPS) : (tid < NMAGS);
      if (valid) {
        float t = 0.f;
#pragma unroll 8
        for (int r = 0; r < 64; r++) t += zz[r * 16 + tid];
        if (isOp) aOp += t; else aMag += t;
      }
    }
    __syncthreads();
    cur ^= 1;
  }

  const size_t base = (size_t)NSTEPS * B;
  if (tid < 64) {
    out[base + 24 + (gb + tid)] = lpsum;             // log_probs.sum(-1)
    out[base + 24 + B + (gb + tid)] = entsum;        // entropies.sum(-1)
  }
  if (tid < 16) {
    g_part[cta * 32 + tid] = aOp;
    g_part[cta * 32 + 16 + tid] = aMag;
  }
}

// ------------- final reduction of prob means -------------
__global__ void reduce_kernel(float* __restrict__ out, int B, int nCTA) {
  int k = threadIdx.x;
  size_t base = (size_t)NSTEPS * B;
  float inv = 1.0f / (20.0f * (float)B);
  if (k < NOPS) {
    float s = 0.f;
    for (int c = 0; c < nCTA; c++) s += g_part[c * 32 + k];
    out[base + k] = s * inv;
  } else if (k >= 16 && k < 16 + NMAGS) {
    int m = k - 16;
    float s = 0.f;
    for (int c = 0; c < nCTA; c++) s += g_part[c * 32 + 16 + m];
    out[base + NOPS + m] = s * inv;
  }
}

extern "C" void kernel_launch(void* const* d_in, const int* in_sizes, int n_in,
                              void* d_out, int out_size) {
  const float* emb  = (const float*)d_in[0];
  const float* Wih  = (const float*)d_in[1];
  const float* Whh  = (const float*)d_in[2];
  const float* bih  = (const float*)d_in[3];
  const float* bhh  = (const float*)d_in[4];
  const float* Wop  = (const float*)d_in[5];
  const float* bop  = (const float*)d_in[6];
  const float* Wmag = (const float*)d_in[7];
  const float* bmag = (const float*)d_in[8];
  float* out = (float*)d_out;

  int B = (out_size - 24) / 42;          // out = 40B policies + 24 means + 2B sums
  if (B <= 0 || B > BMAX) B = BMAX;
  int nCTA = B / 64;

  cudaFuncSetAttribute(main_kernel, cudaFuncAttributeMaxDynamicSharedMemorySize,
                       SM_TOTAL * (int)sizeof(float));

  prep_kernel<<<(HID * HID + 25 * HID + 255) / 256, 256>>>(Wih, Whh, bih, bhh, emb);
  dim3 gg((B * NOPS + 255) / 256, NSTEPS);
  gumbel_kernel<<<gg, 256>>>(B);
  main_kernel<<<nCTA, 256, SM_TOTAL * (int)sizeof(float)>>>(Wop, bop, Wmag, bmag, out, B);
  reduce_kernel<<<1, 32>>>(out, B, nCTA);
}